// round 6
// baseline (speedup 1.0000x reference)
#include <cuda_runtime.h>
#include <cuda_bf16.h>
#include <cstdint>

// AxonalConnections: out[b,t] = sum_s adj[t,s] * (1.5*E[s]-0.5) * spikes[b,s]
// adj is conv-pattern sparse (9 taps per target, boundary-clipped).
//
// R5b: one target row per CTA (128 CTAs, 512 threads).
//  Phase 1 (one global-latency exposure, all loads independent):
//    - 384 threads gather the 3 adjacent adj taps + E, fold, -> wsm.
//    - all 512 threads stage the 3 needed spike rows x 32 batches (48KB)
//      into smem via 6 LDG.128 + 6 STS.128 each (coalesced, MLP=6).
//  Phase 2 (after ONE sync): 72 LDS (29-cyc latency, conflict-free) +
//    72 FMA per thread; halo cols read in-row padded smem values that are
//    multiplied by the already-zero clipped weights.

#define HW 128
#define S_TOT (HW * HW)      // 16384
#define B_TOT 32
#define THREADS 512
#define BPT 8                // batches per thread (4 batch groups)

// Each staged spike row padded to 132 floats: [pad][128 data][3 pad]
#define ROWP 132
#define NROWS (3 * B_TOT)                    // 96 staged rows
#define WSM_FLOATS (9 * HW)                  // 1152
#define SPK_FLOATS (NROWS * ROWP)            // 12672
#define SMEM_BYTES ((WSM_FLOATS + SPK_FLOATS) * 4)   // 55296

extern __shared__ float smem_all[];

__global__ __launch_bounds__(THREADS)
void axonal_r5_kernel(const float* __restrict__ spikes,   // [B, 16384]
                      const float* __restrict__ E,        // [16384]
                      const float* __restrict__ adj,      // [16384, 16384]
                      float* __restrict__ out)            // [B, 16384]
{
    float* wsm = smem_all;                 // [k][tj] folded weights
    float* spk = smem_all + WSM_FLOATS;    // [si_loc][b] rows of ROWP floats

    const int tid = threadIdx.x;
    const int ti  = blockIdx.x;            // target row
    const int t0  = ti * HW;

    // ---- Gather adj+E (threads 0..383): loads issued first ----
    float gw[3];
    int   gk = -1, gtl = 0;
    if (tid < 3 * HW) {
        gtl = tid & (HW - 1);              // target column tj
        const int ki = tid >> 7;           // 0..2
        gk = ki;
        const int t  = t0 + gtl;
        const int si = ti - 1 + ki;
        const bool rowok = (si >= 0) & (si < HW);
        const size_t rowbase = (size_t)t * S_TOT + (size_t)(si * HW);
#pragma unroll
        for (int kj = 0; kj < 3; ++kj) {
            const int sj = gtl - 1 + kj;
            const bool ok = rowok & (sj >= 0) & (sj < HW);
            float w = 0.0f;
            if (ok) {
                const int s = si * HW + sj;
                w = __ldg(&adj[rowbase + (size_t)sj]) *
                    (1.5f * __ldg(&E[s]) - 0.5f);
            }
            gw[kj] = w;
        }
    }

    // ---- Stage 3 spike rows x 32 batches into smem (6 float4 / thread) ----
    // lin = pair*32 + q : pair = (si_loc, b) in 0..95, q = 16B chunk 0..31.
#pragma unroll
    for (int j = 0; j < 6; ++j) {
        const int lin    = tid + j * THREADS;     // 0..3071
        const int pair   = lin >> 5;              // 0..95
        const int q      = lin & 31;              // 0..31 (x4 floats)
        const int si_loc = pair >> 5;             // 0..2
        const int b      = pair & 31;
        const int si     = ti - 1 + si_loc;
        float4 v = make_float4(0.f, 0.f, 0.f, 0.f);
        if (si >= 0 && si < HW) {
            v = *reinterpret_cast<const float4*>(
                    spikes + (size_t)b * S_TOT + (size_t)(si * HW) + q * 4);
        }
        // +1 skips the left-halo pad slot; q*4+1..q*4+4 within the row.
        float* dst = spk + pair * ROWP + 1 + q * 4;
        dst[0] = v.x; dst[1] = v.y; dst[2] = v.z; dst[3] = v.w;
    }

    // ---- Publish folded weights ----
    if (gk >= 0) {
#pragma unroll
        for (int kj = 0; kj < 3; ++kj)
            wsm[(gk * 3 + kj) * HW + gtl] = gw[kj];
    }
    __syncthreads();

    // ---- Compute: pure LDS + FMA ----
    const int tloc = tid & (HW - 1);       // target column (coalesced)
    const int bg   = tid >> 7;             // 0..3
    const int t    = t0 + tloc;

    float w[9];
#pragma unroll
    for (int k = 0; k < 9; ++k)
        w[k] = wsm[k * HW + tloc];         // consecutive lanes -> no conflicts

#pragma unroll
    for (int bb = 0; bb < BPT; ++bb) {
        const int b = bg * BPT + bb;
        float a0 = 0.f, a1 = 0.f, a2 = 0.f;
#pragma unroll
        for (int ki = 0; ki < 3; ++ki) {
            // +1: data starts one slot into the padded row.
            const float* row = spk + (ki * B_TOT + b) * ROWP + 1 + tloc;
            // row[-1]/row[+1] at grid edges hit the in-row pad slots (or
            // stale data multiplied by exactly-zero weights) - always in smem.
            a0 = fmaf(w[ki * 3 + 0], row[-1], a0);
            a1 = fmaf(w[ki * 3 + 1], row[ 0], a1);
            a2 = fmaf(w[ki * 3 + 2], row[ 1], a2);
        }
        out[(size_t)b * S_TOT + t] = a0 + a1 + a2;
    }
}

extern "C" void kernel_launch(void* const* d_in, const int* in_sizes, int n_in,
                              void* d_out, int out_size)
{
    // Identify inputs by element count:
    //   spikes: 524288, E: 16384, adjacency: 268435456
    const float* spikes = nullptr;
    const float* E      = nullptr;
    const float* adj    = nullptr;
    for (int i = 0; i < n_in; ++i) {
        if (in_sizes[i] == B_TOT * S_TOT)  spikes = (const float*)d_in[i];
        else if (in_sizes[i] == S_TOT)     E      = (const float*)d_in[i];
        else                               adj    = (const float*)d_in[i];
    }
    float* out = (float*)d_out;

    cudaFuncSetAttribute(axonal_r5_kernel,
                         cudaFuncAttributeMaxDynamicSharedMemorySize,
                         SMEM_BYTES);
    axonal_r5_kernel<<<HW, THREADS, SMEM_BYTES>>>(spikes, E, adj, out);
}

// round 8
// speedup vs baseline: 1.2098x; 1.2098x over previous
#include <cuda_runtime.h>
#include <cuda_bf16.h>
#include <cstdint>

// AxonalConnections: out[b,t] = sum_s adj[t,s] * (1.5*E[s]-0.5) * spikes[b,s]
// adj is conv-pattern sparse (9 taps per target, boundary-clipped).
//
// R7 (re-bench; previous round hit a GPU-acquisition timeout, kernel never ran):
// R3 dataflow (gather adj once per CTA -> smem weights, direct global spike
// loads) at finer CTA granularity for perfect wave balance:
//   512 CTAs x 256 threads, TPC=32 targets, all 32 batches per CTA.
//   All 512 CTAs are simultaneously resident (single balanced wave; CTA
//   staggering overlaps phase-1 gather latency with other CTAs' phase-2).

#define HW 128
#define S_TOT (HW * HW)      // 16384
#define B_TOT 32
#define TPC 32               // targets per CTA
#define THREADS 256          // 32 targets x 8 batch groups
#define BPT 4                // batches per thread

__global__ __launch_bounds__(THREADS)
void axonal_r7_kernel(const float* __restrict__ spikes,   // [B, 16384]
                      const float* __restrict__ E,        // [16384]
                      const float* __restrict__ adj,      // [16384, 16384]
                      float* __restrict__ out)            // [B, 16384]
{
    __shared__ float wsm[9 * TPC];       // [k][tloc] folded weights

    const int tid = threadIdx.x;
    const int t0  = blockIdx.x * TPC;

    // ---- Phase 1: gather 3 adjacent adj taps + E per thread, fold ----
    if (tid < 3 * TPC) {
        const int tloc = tid & (TPC - 1);
        const int ki   = tid / TPC;              // 0..2
        const int t    = t0 + tloc;
        const int ti   = t >> 7;
        const int tj   = t & (HW - 1);
        const int si   = ti - 1 + ki;
        const bool rowok = (si >= 0) & (si < HW);
        const size_t rowbase = (size_t)t * S_TOT + (size_t)(si * HW);
#pragma unroll
        for (int kj = 0; kj < 3; ++kj) {
            const int sj = tj - 1 + kj;
            const bool ok = rowok & (sj >= 0) & (sj < HW);
            float w = 0.0f;
            if (ok) {
                const int s = si * HW + sj;
                w = __ldg(&adj[rowbase + (size_t)sj]) *
                    (1.5f * __ldg(&E[s]) - 0.5f);
            }
            wsm[(ki * 3 + kj) * TPC + tloc] = w;
        }
    }
    __syncthreads();

    // ---- Phase 2: 9-tap FMA per (target, batch), 4 batches/thread ----
    const int tloc = tid & (TPC - 1);    // coalesced across warp
    const int bg   = tid / TPC;          // 0..7
    const int t    = t0 + tloc;
    const int ti   = t >> 7;
    const int tj   = t & (HW - 1);

    // Tap indices computed arithmetically (clipped -> weight already 0).
    int so[9];
#pragma unroll
    for (int k = 0; k < 9; ++k) {
        const int ki = k / 3, kj = k - 3 * ki;
        const int si = ti - 1 + ki;
        const int sj = tj - 1 + kj;
        const bool ok = (si >= 0) & (si < HW) & (sj >= 0) & (sj < HW);
        so[k] = ok ? (si * HW + sj) : 0;
    }

    float w[9];
#pragma unroll
    for (int k = 0; k < 9; ++k)
        w[k] = wsm[k * TPC + tloc];      // conflict-free (consecutive banks)

#pragma unroll
    for (int bb = 0; bb < BPT; ++bb) {
        const int b = bg * BPT + bb;
        const float* __restrict__ sp = spikes + (size_t)b * S_TOT;
        float a0 = w[0] * __ldg(&sp[so[0]]);
        float a1 = w[1] * __ldg(&sp[so[1]]);
        float a2 = w[2] * __ldg(&sp[so[2]]);
        a0 = fmaf(w[3], __ldg(&sp[so[3]]), a0);
        a1 = fmaf(w[4], __ldg(&sp[so[4]]), a1);
        a2 = fmaf(w[5], __ldg(&sp[so[5]]), a2);
        a0 = fmaf(w[6], __ldg(&sp[so[6]]), a0);
        a1 = fmaf(w[7], __ldg(&sp[so[7]]), a1);
        a2 = fmaf(w[8], __ldg(&sp[so[8]]), a2);
        out[(size_t)b * S_TOT + t] = a0 + a1 + a2;
    }
}

extern "C" void kernel_launch(void* const* d_in, const int* in_sizes, int n_in,
                              void* d_out, int out_size)
{
    // Identify inputs by element count:
    //   spikes: 524288, E: 16384, adjacency: 268435456
    const float* spikes = nullptr;
    const float* E      = nullptr;
    const float* adj    = nullptr;
    for (int i = 0; i < n_in; ++i) {
        if (in_sizes[i] == B_TOT * S_TOT)  spikes = (const float*)d_in[i];
        else if (in_sizes[i] == S_TOT)     E      = (const float*)d_in[i];
        else                               adj    = (const float*)d_in[i];
    }
    float* out = (float*)d_out;

    axonal_r7_kernel<<<S_TOT / TPC, THREADS>>>(spikes, E, adj, out);  // 512 CTAs
}